// round 3
// baseline (speedup 1.0000x reference)
#include <cuda_runtime.h>
#include <cuda_bf16.h>
#include <math.h>

// Problem constants
#define ADIM 8
#define BDIM 16
#define HDIM 64
#define WDIM 64
#define SPATIAL (ADIM*BDIM*HDIM*WDIM)   // 524288 = 2^19
#define COUT 32
#define EPSV 1e-5f
#define NEG_SLOPE 0.2f

// Scratch (static device globals; runtime allocation is forbidden)
__device__ float g_buf1[COUT * SPATIAL];   // conv1 output / normalized act
__device__ float g_buf2[COUT * SPATIAL];   // conv2 output
__device__ float2 g_stats1[COUT];          // (mean, rstd)
__device__ float2 g_stats2[COUT];

// ---------------------------------------------------------------------------
// Direct 4D conv, kernel 3x3x3x3, pad 1, stride 1.
// Block: 256 threads -> tile 32(H) x 64(W, full row) at fixed (a,b), 8 couts.
// Thread: 2(H) x 4(W) pixels x 8 couts = 64 accumulators.
// Loop over (da, db, cin); one 34x66 halo plane in smem per iteration.
// ---------------------------------------------------------------------------
template<int CIN>
__global__ __launch_bounds__(256)
void conv4d_kernel(const float* __restrict__ x,   // [CIN][A][B][H][W]
                   const float* __restrict__ w,   // [COUT][CIN][3][3][3][3]
                   float* __restrict__ y)         // [COUT][A][B][H][W]
{
    const int ab  = blockIdx.x;          // 0..127
    const int a   = ab >> 4;             // 0..7
    const int b   = ab & 15;             // 0..15
    const int h0  = blockIdx.y * 32;     // 0 or 32
    const int co0 = blockIdx.z * 8;      // 0,8,16,24

    const int tid = threadIdx.x;
    const int tx  = tid & 15;            // w-group: pixels tx*4 .. tx*4+3
    const int ty  = tid >> 4;            // h-group: pixels h0+ty*2, +1

    __shared__ float splane[34 * 66];    // halo'd input plane (row stride 66)
    __shared__ float wsm[8][9];          // 8 couts x 9 (kh,kw) taps

    float acc[8][2][4];
    #pragma unroll
    for (int c = 0; c < 8; ++c)
        #pragma unroll
        for (int p = 0; p < 2; ++p)
            #pragma unroll
            for (int q = 0; q < 4; ++q) acc[c][p][q] = 0.f;

    for (int da = 0; da < 3; ++da) {
        const int ia = a + da - 1;
        if ((unsigned)ia >= (unsigned)ADIM) continue;   // whole plane zero
        for (int db = 0; db < 3; ++db) {
            const int ib = b + db - 1;
            if ((unsigned)ib >= (unsigned)BDIM) continue;

            for (int ci = 0; ci < CIN; ++ci) {
                __syncthreads();   // protect smem from previous iteration's readers

                // --- load 34x66 halo plane (zero-padded H/W borders) ---
                const float* xp = x + (((size_t)ci * ADIM + ia) * BDIM + ib) * (HDIM * WDIM);
                #pragma unroll 3
                for (int i = tid; i < 34 * 66; i += 256) {
                    const int r = i / 66;
                    const int c = i - r * 66;
                    const int hh = h0 - 1 + r;
                    const int ww = c - 1;
                    float v = 0.f;
                    if ((unsigned)hh < (unsigned)HDIM && (unsigned)ww < (unsigned)WDIM)
                        v = xp[hh * WDIM + ww];
                    splane[i] = v;
                }
                // --- load 8x9 weights for this (ci, da, db) ---
                if (tid < 72) {
                    const int co = tid / 9;
                    const int t  = tid - co * 9;           // kh*3+kw
                    wsm[co][t] = w[((((size_t)(co0 + co) * CIN + ci) * 3 + da) * 3 + db) * 9 + t];
                }
                __syncthreads();

                // --- gather 4x6 input patch into registers ---
                float xr[4][6];
                const int rbase = ty * 2;      // smem row of (pixel_h - 1)
                const int cbase = tx * 4;      // smem col of (pixel_w - 1)
                #pragma unroll
                for (int r = 0; r < 4; ++r)
                    #pragma unroll
                    for (int c = 0; c < 6; ++c)
                        xr[r][c] = splane[(rbase + r) * 66 + cbase + c];

                // --- accumulate: 8 couts x 9 taps x 8 pixels = 576 FMA ---
                #pragma unroll
                for (int co = 0; co < 8; ++co) {
                    float wv[9];
                    #pragma unroll
                    for (int t = 0; t < 9; ++t) wv[t] = wsm[co][t];
                    #pragma unroll
                    for (int ph = 0; ph < 2; ++ph)
                        #pragma unroll
                        for (int pw = 0; pw < 4; ++pw) {
                            float s = acc[co][ph][pw];
                            s = fmaf(wv[0], xr[ph + 0][pw + 0], s);
                            s = fmaf(wv[1], xr[ph + 0][pw + 1], s);
                            s = fmaf(wv[2], xr[ph + 0][pw + 2], s);
                            s = fmaf(wv[3], xr[ph + 1][pw + 0], s);
                            s = fmaf(wv[4], xr[ph + 1][pw + 1], s);
                            s = fmaf(wv[5], xr[ph + 1][pw + 2], s);
                            s = fmaf(wv[6], xr[ph + 2][pw + 0], s);
                            s = fmaf(wv[7], xr[ph + 2][pw + 1], s);
                            s = fmaf(wv[8], xr[ph + 2][pw + 2], s);
                            acc[co][ph][pw] = s;
                        }
                }
            }
        }
    }

    // --- epilogue: float4 stores ---
    #pragma unroll
    for (int co = 0; co < 8; ++co) {
        float* yb = y + (((size_t)(co0 + co) * ADIM + a) * BDIM + b) * (HDIM * WDIM);
        #pragma unroll
        for (int ph = 0; ph < 2; ++ph) {
            const int hh = h0 + ty * 2 + ph;
            float4 v = make_float4(acc[co][ph][0], acc[co][ph][1],
                                   acc[co][ph][2], acc[co][ph][3]);
            *reinterpret_cast<float4*>(yb + hh * WDIM + tx * 4) = v;
        }
    }
}

// ---------------------------------------------------------------------------
// Per-channel mean / rstd over SPATIAL elements. One block per channel,
// deterministic (no float atomics).
// ---------------------------------------------------------------------------
__global__ __launch_bounds__(1024)
void stats_kernel(const float* __restrict__ buf, float2* __restrict__ stats)
{
    const int co = blockIdx.x;
    const float4* p = reinterpret_cast<const float4*>(buf + (size_t)co * SPATIAL);
    const int nvec = SPATIAL / 4;   // 131072

    float s = 0.f, s2 = 0.f;
    for (int i = threadIdx.x; i < nvec; i += 1024) {
        float4 v = p[i];
        s  += v.x + v.y + v.z + v.w;
        s2 += v.x * v.x + v.y * v.y + v.z * v.z + v.w * v.w;
    }
    // warp reduce
    #pragma unroll
    for (int o = 16; o > 0; o >>= 1) {
        s  += __shfl_down_sync(0xffffffffu, s,  o);
        s2 += __shfl_down_sync(0xffffffffu, s2, o);
    }
    __shared__ float rs[32], rs2[32];
    const int lane = threadIdx.x & 31, wid = threadIdx.x >> 5;
    if (lane == 0) { rs[wid] = s; rs2[wid] = s2; }
    __syncthreads();
    if (wid == 0) {
        s  = rs[lane];
        s2 = rs2[lane];
        #pragma unroll
        for (int o = 16; o > 0; o >>= 1) {
            s  += __shfl_down_sync(0xffffffffu, s,  o);
            s2 += __shfl_down_sync(0xffffffffu, s2, o);
        }
        if (lane == 0) {
            const float inv_n = 1.0f / (float)SPATIAL;
            const float mean  = s * inv_n;
            const float var   = fmaxf(s2 * inv_n - mean * mean, 0.f);
            stats[co] = make_float2(mean, rsqrtf(var + EPSV));
        }
    }
}

// ---------------------------------------------------------------------------
// out = leaky_relu((in - mean) * rstd), per-channel scalars. float4 vectorized.
// ---------------------------------------------------------------------------
__global__ __launch_bounds__(256)
void normleaky_kernel(const float* __restrict__ in,
                      const float2* __restrict__ stats,
                      float* __restrict__ out)
{
    const int nvec = COUT * SPATIAL / 4;     // 4194304
    const float4* ip = reinterpret_cast<const float4*>(in);
    float4* op = reinterpret_cast<float4*>(out);
    for (int i = blockIdx.x * blockDim.x + threadIdx.x; i < nvec;
         i += gridDim.x * blockDim.x) {
        const int co = (i * 4) >> 19;        // SPATIAL = 2^19
        const float2 st = stats[co];
        float4 v = ip[i];
        float a0 = (v.x - st.x) * st.y;
        float a1 = (v.y - st.x) * st.y;
        float a2 = (v.z - st.x) * st.y;
        float a3 = (v.w - st.x) * st.y;
        v.x = a0 >= 0.f ? a0 : NEG_SLOPE * a0;
        v.y = a1 >= 0.f ? a1 : NEG_SLOPE * a1;
        v.z = a2 >= 0.f ? a2 : NEG_SLOPE * a2;
        v.w = a3 >= 0.f ? a3 : NEG_SLOPE * a3;
        op[i] = v;
    }
}

// ---------------------------------------------------------------------------
// kernel_launch: conv1 -> stats -> norm+leaky (in-place) -> conv2 -> stats
//                -> norm+leaky -> d_out
// ---------------------------------------------------------------------------
extern "C" void kernel_launch(void* const* d_in, const int* in_sizes, int n_in,
                              void* d_out, int out_size)
{
    (void)in_sizes; (void)n_in; (void)out_size;
    const float* image = (const float*)d_in[0];  // (1,16,8,16,64,64)
    const float* w1    = (const float*)d_in[1];  // (32,16,3,3,3,3)
    const float* w2    = (const float*)d_in[2];  // (32,32,3,3,3,3)
    float* out = (float*)d_out;

    float*  buf1; cudaGetSymbolAddress((void**)&buf1, g_buf1);
    float*  buf2; cudaGetSymbolAddress((void**)&buf2, g_buf2);
    float2* st1;  cudaGetSymbolAddress((void**)&st1,  g_stats1);
    float2* st2;  cudaGetSymbolAddress((void**)&st2,  g_stats2);

    const dim3 cgrid(ADIM * BDIM, HDIM / 32, COUT / 8);  // (128, 2, 4)

    conv4d_kernel<16><<<cgrid, 256>>>(image, w1, buf1);
    stats_kernel<<<COUT, 1024>>>(buf1, st1);
    normleaky_kernel<<<2048, 256>>>(buf1, st1, buf1);

    conv4d_kernel<32><<<cgrid, 256>>>(buf1, w2, buf2);
    stats_kernel<<<COUT, 1024>>>(buf2, st2);
    normleaky_kernel<<<2048, 256>>>(buf2, st2, out);
}

// round 6
// speedup vs baseline: 1.3156x; 1.3156x over previous
#include <cuda_runtime.h>
#include <cuda_bf16.h>
#include <math.h>
#include <stdint.h>

// Problem constants
#define ADIM 8
#define BDIM 16
#define HDIM 64
#define WDIM 64
#define SPATIAL (ADIM*BDIM*HDIM*WDIM)   // 524288 = 2^19
#define COUT 32
#define EPSV 1e-5f
#define NEG_SLOPE 0.2f

typedef unsigned long long ull;

// Scratch (static device globals; runtime allocation is forbidden)
__device__ float g_buf1[COUT * SPATIAL];
__device__ float g_buf2[COUT * SPATIAL];
__device__ float2 g_stats1[COUT];
__device__ float2 g_stats2[COUT];

// ---------------------------------------------------------------------------
// Packed fp32 helpers
// ---------------------------------------------------------------------------
#define FMA2(d, a, b) \
    asm volatile("fma.rn.f32x2 %0, %1, %2, %0;" : "+l"(d) : "l"(a), "l"(b))

// u = (hi(a), lo(b))  -- the unaligned middle pair
#define MIDPAIR(u, a, b) \
    asm volatile("{\n\t.reg .b32 l1, h1, l2, h2;\n\t" \
                 "mov.b64 {l1,h1}, %1;\n\t" \
                 "mov.b64 {l2,h2}, %2;\n\t" \
                 "mov.b64 %0, {h1, l2};\n\t}" \
                 : "=l"(u) : "l"(a), "l"(b))

__device__ __forceinline__ void cp_async4(uint32_t sa, const void* g, int sz) {
    asm volatile("cp.async.ca.shared.global [%0], [%1], 4, %2;"
                 :: "r"(sa), "l"(g), "r"(sz));
}
#define CP_COMMIT() asm volatile("cp.async.commit_group;")
#define CP_WAIT0()  asm volatile("cp.async.wait_group 0;")
#define CP_WAIT1()  asm volatile("cp.async.wait_group 1;")

// ---------------------------------------------------------------------------
// Async halo-plane loader: rows 0..33 (hh = h0-1+r, zero-filled OOB),
// cols 1..64 of a 66-wide row. Border cols 0 and 65 are pre-zeroed once.
// 34*64 = 2176 elements, 4B cp.async each, zero-fill via src-size=0.
// ---------------------------------------------------------------------------
__device__ __forceinline__ void load_plane(float* sdst, const float* xp,
                                           int h0, int tid)
{
    #pragma unroll
    for (int k = 0; k < 9; ++k) {
        const int e = tid + (k << 8);
        if (e < 34 * 64) {
            const int r  = e >> 6;
            const int cc = e & 63;
            const int hh = h0 - 1 + r;
            const bool ok = (unsigned)hh < (unsigned)HDIM;
            uint32_t sa = (uint32_t)__cvta_generic_to_shared(sdst + r * 66 + 1 + cc);
            const float* g = xp + (size_t)(ok ? hh : 0) * WDIM + cc;
            cp_async4(sa, g, ok ? 4 : 0);
        }
    }
}

// ---------------------------------------------------------------------------
// Direct 4D conv, 3x3x3x3, pad 1. Packed f32x2 math.
// Block: 256 thr -> tile 32(H) x 64(W) at fixed (a,b), 8 couts.
// Thread: 2(H) x 4(W) pixels x 8 couts; accs packed over pw pairs.
// cp.async double-buffered input planes; weights duplicated {w,w} in smem.
// ---------------------------------------------------------------------------
template<int CIN>
__global__ __launch_bounds__(256, 2)
void conv4d_kernel(const float* __restrict__ x,   // [CIN][A][B][H][W]
                   const float* __restrict__ w,   // [COUT][CIN][3][3][3][3]
                   float* __restrict__ y)         // [COUT][A][B][H][W]
{
    const int ab  = blockIdx.x;
    const int a   = ab >> 4;
    const int b   = ab & 15;
    const int h0  = blockIdx.y * 32;
    const int co0 = blockIdx.z * 8;

    const int tid = threadIdx.x;
    const int tx  = tid & 15;            // pw base = tx*4 (4 consecutive pixels)
    const int ty  = tid >> 4;            // h rows h0+ty*2, +1
    const int rbase = ty * 2;
    const int cbase = tx * 4;

    __shared__ __align__(16) float  splane[2][34 * 66];   // 2 x 8.98 KB
    __shared__ __align__(8)  float2 wsm[CIN * 72];        // [ci][tap][co] dup pairs

    // Pre-zero the always-zero border columns (ww=-1 -> c=0, ww=64 -> c=65)
    if (tid < 136) {
        const int bf   = tid & 1;
        const int rest = tid >> 1;      // 0..67
        const int r    = rest >> 1;     // 0..33
        const int cl   = (rest & 1) * 65;
        splane[bf][r * 66 + cl] = 0.f;
    }

    // Packed accumulators: [co][ph][pw-pair], each ull = {out[pw], out[pw+1]}
    ull acc[8][2][2];
    #pragma unroll
    for (int c = 0; c < 8; ++c)
        #pragma unroll
        for (int p = 0; p < 2; ++p) {
            acc[c][p][0] = 0ull;
            acc[c][p][1] = 0ull;
        }

    int buf = 0;

    for (int da = 0; da < 3; ++da) {
        const int ia = a + da - 1;
        if ((unsigned)ia >= (unsigned)ADIM) continue;
        for (int db = 0; db < 3; ++db) {
            const int ib = b + db - 1;
            if ((unsigned)ib >= (unsigned)BDIM) continue;

            const float* xab = x + ((size_t)ia * BDIM + ib) * (HDIM * WDIM);
            const int tapidx = da * 3 + db;

            // Fill duplicated weights for this (da,db): wsm[(ci*9+tap)*8+co]
            for (int t = tid; t < CIN * 72; t += 256) {
                const int co   = t & 7;
                const int rest = t >> 3;       // ci*9 + tap
                const int tap  = rest % 9;
                const int ci   = rest / 9;
                const float wv = w[((size_t)(co0 + co) * CIN + ci) * 81
                                   + tapidx * 9 + tap];
                wsm[t] = make_float2(wv, wv);
            }

            // Prologue: stream plane ci=0
            load_plane(splane[buf], xab, h0, tid);
            CP_COMMIT();

            for (int ci = 0; ci < CIN; ++ci) {
                const int nb = buf ^ 1;
                if (ci + 1 < CIN) {
                    load_plane(splane[nb], xab + (size_t)(ci + 1) * SPATIAL, h0, tid);
                    CP_COMMIT();
                    CP_WAIT1();              // plane ci complete (1 group pending)
                } else {
                    CP_WAIT0();
                }
                __syncthreads();             // plane ci + weights visible to all

                const float*  pl  = splane[buf];
                const float2* wci = wsm + ci * 72;

                #pragma unroll
                for (int kh = 0; kh < 3; ++kh) {
                    const float* r0 = pl + (rbase + kh) * 66 + cbase;
                    // Aligned pairs (s0,s1)(s2,s3)(s4,s5) for ph=0 (A) and ph=1 (B)
                    ull A0 = *(const ull*)(r0);
                    ull A1 = *(const ull*)(r0 + 2);
                    ull A2 = *(const ull*)(r0 + 4);
                    ull B0 = *(const ull*)(r0 + 66);
                    ull B1 = *(const ull*)(r0 + 68);
                    ull B2 = *(const ull*)(r0 + 70);
                    ull Au0, Au1, Bu0, Bu1;   // (s1,s2), (s3,s4)
                    MIDPAIR(Au0, A0, A1);  MIDPAIR(Au1, A1, A2);
                    MIDPAIR(Bu0, B0, B1);  MIDPAIR(Bu1, B1, B2);

                    #pragma unroll
                    for (int kw = 0; kw < 3; ++kw) {
                        const ull xa0 = (kw == 0) ? A0 : (kw == 1) ? Au0 : A1;
                        const ull xa1 = (kw == 0) ? A1 : (kw == 1) ? Au1 : A2;
                        const ull xb0 = (kw == 0) ? B0 : (kw == 1) ? Bu0 : B1;
                        const ull xb1 = (kw == 0) ? B1 : (kw == 1) ? Bu1 : B2;
                        const float2* wt = wci + (kh * 3 + kw) * 8;
                        #pragma unroll
                        for (int co = 0; co < 8; ++co) {
                            const ull ww = *(const ull*)(wt + co);  // broadcast LDS.64
                            FMA2(acc[co][0][0], ww, xa0);
                            FMA2(acc[co][0][1], ww, xa1);
                            FMA2(acc[co][1][0], ww, xb0);
                            FMA2(acc[co][1][1], ww, xb1);
                        }
                    }
                }
                __syncthreads();   // compute done before this buffer is overwritten
                buf = nb;
            }
        }
    }

    // Epilogue: unpack pairs, float4 stores
    #pragma unroll
    for (int co = 0; co < 8; ++co) {
        float* yb = y + (((size_t)(co0 + co) * ADIM + a) * BDIM + b) * (HDIM * WDIM);
        #pragma unroll
        for (int ph = 0; ph < 2; ++ph) {
            const float2 v0 = *reinterpret_cast<const float2*>(&acc[co][ph][0]);
            const float2 v1 = *reinterpret_cast<const float2*>(&acc[co][ph][1]);
            const int hh = h0 + rbase + ph;
            *reinterpret_cast<float4*>(yb + hh * WDIM + cbase) =
                make_float4(v0.x, v0.y, v1.x, v1.y);
        }
    }
}

// ---------------------------------------------------------------------------
// Per-channel mean / rstd. One block per channel, deterministic.
// ---------------------------------------------------------------------------
__global__ __launch_bounds__(1024)
void stats_kernel(const float* __restrict__ buf, float2* __restrict__ stats)
{
    const int co = blockIdx.x;
    const float4* p = reinterpret_cast<const float4*>(buf + (size_t)co * SPATIAL);
    const int nvec = SPATIAL / 4;

    float s = 0.f, s2 = 0.f;
    for (int i = threadIdx.x; i < nvec; i += 1024) {
        float4 v = p[i];
        s  += v.x + v.y + v.z + v.w;
        s2 += v.x * v.x + v.y * v.y + v.z * v.z + v.w * v.w;
    }
    #pragma unroll
    for (int o = 16; o > 0; o >>= 1) {
        s  += __shfl_down_sync(0xffffffffu, s,  o);
        s2 += __shfl_down_sync(0xffffffffu, s2, o);
    }
    __shared__ float rs[32], rs2[32];
    const int lane = threadIdx.x & 31, wid = threadIdx.x >> 5;
    if (lane == 0) { rs[wid] = s; rs2[wid] = s2; }
    __syncthreads();
    if (wid == 0) {
        s  = rs[lane];
        s2 = rs2[lane];
        #pragma unroll
        for (int o = 16; o > 0; o >>= 1) {
            s  += __shfl_down_sync(0xffffffffu, s,  o);
            s2 += __shfl_down_sync(0xffffffffu, s2, o);
        }
        if (lane == 0) {
            const float inv_n = 1.0f / (float)SPATIAL;
            const float mean  = s * inv_n;
            const float var   = fmaxf(s2 * inv_n - mean * mean, 0.f);
            stats[co] = make_float2(mean, rsqrtf(var + EPSV));
        }
    }
}

// ---------------------------------------------------------------------------
// out = leaky_relu((in - mean) * rstd)
// ---------------------------------------------------------------------------
__global__ __launch_bounds__(256)
void normleaky_kernel(const float* __restrict__ in,
                      const float2* __restrict__ stats,
                      float* __restrict__ out)
{
    const int nvec = COUT * SPATIAL / 4;
    const float4* ip = reinterpret_cast<const float4*>(in);
    float4* op = reinterpret_cast<float4*>(out);
    for (int i = blockIdx.x * blockDim.x + threadIdx.x; i < nvec;
         i += gridDim.x * blockDim.x) {
        const int co = (i * 4) >> 19;
        const float2 st = stats[co];
        float4 v = ip[i];
        float a0 = (v.x - st.x) * st.y;
        float a1 = (v.y - st.x) * st.y;
        float a2 = (v.z - st.x) * st.y;
        float a3 = (v.w - st.x) * st.y;
        v.x = a0 >= 0.f ? a0 : NEG_SLOPE * a0;
        v.y = a1 >= 0.f ? a1 : NEG_SLOPE * a1;
        v.z = a2 >= 0.f ? a2 : NEG_SLOPE * a2;
        v.w = a3 >= 0.f ? a3 : NEG_SLOPE * a3;
        op[i] = v;
    }
}

// ---------------------------------------------------------------------------
extern "C" void kernel_launch(void* const* d_in, const int* in_sizes, int n_in,
                              void* d_out, int out_size)
{
    (void)in_sizes; (void)n_in; (void)out_size;
    const float* image = (const float*)d_in[0];
    const float* w1    = (const float*)d_in[1];
    const float* w2    = (const float*)d_in[2];
    float* out = (float*)d_out;

    float*  buf1; cudaGetSymbolAddress((void**)&buf1, g_buf1);
    float*  buf2; cudaGetSymbolAddress((void**)&buf2, g_buf2);
    float2* st1;  cudaGetSymbolAddress((void**)&st1,  g_stats1);
    float2* st2;  cudaGetSymbolAddress((void**)&st2,  g_stats2);

    const dim3 cgrid(ADIM * BDIM, HDIM / 32, COUT / 8);  // (128, 2, 4)

    conv4d_kernel<16><<<cgrid, 256>>>(image, w1, buf1);
    stats_kernel<<<COUT, 1024>>>(buf1, st1);
    normleaky_kernel<<<2048, 256>>>(buf1, st1, buf1);

    conv4d_kernel<32><<<cgrid, 256>>>(buf1, w2, buf2);
    stats_kernel<<<COUT, 1024>>>(buf2, st2);
    normleaky_kernel<<<2048, 256>>>(buf2, st2, out);
}